// round 6
// baseline (speedup 1.0000x reference)
#include <cuda_runtime.h>
#include <cuda_bf16.h>
#include <math.h>

// Problem dims (fixed per reference)
#define BATCH 4
#define SEQ   2048
#define DMODEL 1024
#define DK    128
#define MTOT  (BATCH*SEQ)   // 8192

// ---------------- scratch (device globals; no allocation allowed) -----------
__device__ float g_Q[MTOT * DK];
__device__ float g_K[MTOT * DK];
__device__ float g_V[MTOT * DK];
__device__ float g_O[MTOT * DK];

// ---------------- generic 64x128 SGEMM body ---------------------------------
// C[M,N] = A[M,K] * B[K,N], row-major. BM=64, BN=128, BK=16, 256 threads.
#define BM 64
#define BN 128
#define BKG 16
#define AS_LD 68   // padded

__device__ __forceinline__ void sgemm_body(
    const float* __restrict__ A, const float* __restrict__ B, float* __restrict__ C,
    int N, int K, int m0, int n0,
    float (*As)[AS_LD], float (*Bs)[BN])
{
    const int tid = threadIdx.x;
    const int tx = tid & 31;        // 0..31  (col groups of 4)
    const int ty = tid >> 5;        // 0..7   (row groups of 8)

    const int arow = tid >> 2;          // 0..63
    const int acol = (tid & 3) << 2;    // 0,4,8,12

    float acc[8][4];
#pragma unroll
    for (int r = 0; r < 8; ++r)
#pragma unroll
        for (int c = 0; c < 4; ++c) acc[r][c] = 0.f;

    for (int k0 = 0; k0 < K; k0 += BKG) {
        // load A tile (64x16), store transposed As[k][row]
        float4 a = *(const float4*)&A[(size_t)(m0 + arow) * K + k0 + acol];
        As[acol + 0][arow] = a.x;
        As[acol + 1][arow] = a.y;
        As[acol + 2][arow] = a.z;
        As[acol + 3][arow] = a.w;
        // load B tile (16x128), 2 float4 per thread
        {
            int idx = tid;
            int r = idx >> 5, c = (idx & 31) << 2;
            *(float4*)&Bs[r][c] = *(const float4*)&B[(size_t)(k0 + r) * N + n0 + c];
            idx = tid + 256;
            r = idx >> 5; c = (idx & 31) << 2;
            *(float4*)&Bs[r][c] = *(const float4*)&B[(size_t)(k0 + r) * N + n0 + c];
        }
        __syncthreads();
#pragma unroll
        for (int k = 0; k < BKG; ++k) {
            float4 a0 = *(float4*)&As[k][ty * 8];
            float4 a1 = *(float4*)&As[k][ty * 8 + 4];
            float4 b  = *(float4*)&Bs[k][tx * 4];
            float ar[8] = {a0.x,a0.y,a0.z,a0.w,a1.x,a1.y,a1.z,a1.w};
            float br[4] = {b.x,b.y,b.z,b.w};
#pragma unroll
            for (int r = 0; r < 8; ++r)
#pragma unroll
                for (int c = 0; c < 4; ++c)
                    acc[r][c] = fmaf(ar[r], br[c], acc[r][c]);
        }
        __syncthreads();
    }
#pragma unroll
    for (int r = 0; r < 8; ++r) {
        float4 o = make_float4(acc[r][0], acc[r][1], acc[r][2], acc[r][3]);
        *(float4*)&C[(size_t)(m0 + ty * 8 + r) * N + n0 + tx * 4] = o;
    }
}

// QKV projection: grid (1, M/64, 3)
__global__ __launch_bounds__(256) void qkv_gemm_kernel(
    const float* __restrict__ x,
    const float* __restrict__ Wq,
    const float* __restrict__ Wk,
    const float* __restrict__ Wv)
{
    __shared__ float As[BKG][AS_LD];
    __shared__ float Bs[BKG][BN];
    const float* W;
    float* out;
    if (blockIdx.z == 0)      { W = Wq; out = g_Q; }
    else if (blockIdx.z == 1) { W = Wk; out = g_K; }
    else                      { W = Wv; out = g_V; }
    sgemm_body(x, W, out, DK, DMODEL, blockIdx.y * BM, blockIdx.x * BN, As, Bs);
}

// Output projection: grid (DMODEL/128, M/64)
__global__ __launch_bounds__(256) void out_gemm_kernel(
    const float* __restrict__ Wo, float* __restrict__ out)
{
    __shared__ float As[BKG][AS_LD];
    __shared__ float Bs[BKG][BN];
    sgemm_body(g_O, Wo, out, DMODEL, DK, blockIdx.y * BM, blockIdx.x * BN, As, Bs);
}

// ---------------- flash attention (causal) -----------------------------------
// BQ=64, BKV=64, DH=128. 256 threads = 16x16.
// S phase: thread (tx,ty): q-rows ty*4..+3, k-cols tx*4..+3.
// O phase: same rows, d-cols tx*8..+7.
#define QS_LD 132
#define PS_LD 65
#define ATT_SMEM ((3 * 64 * QS_LD + 64 * PS_LD) * sizeof(float))

__global__ __launch_bounds__(256) void flash_attn_kernel()
{
    extern __shared__ float sm[];
    float* Qs = sm;                     // 64 x 132
    float* Ks = Qs + 64 * QS_LD;        // 64 x 132
    float* Vs = Ks + 64 * QS_LD;        // 64 x 132
    float* Ps = Vs + 64 * QS_LD;        // 64 x 65

    const int tid = threadIdx.x;
    const int tx = tid & 15;
    const int ty = tid >> 4;
    const int b  = blockIdx.y;
    const int q0 = blockIdx.x * 64;

    const float* Qg = g_Q + (size_t)b * SEQ * DK;
    const float* Kg = g_K + (size_t)b * SEQ * DK;
    const float* Vg = g_V + (size_t)b * SEQ * DK;

    // load Q tile
#pragma unroll
    for (int t = 0; t < 8; ++t) {
        int e = t * 256 + tid;               // float4 index, 0..2047
        int row = e >> 5, c4 = (e & 31) << 2;
        *(float4*)&Qs[row * QS_LD + c4] = *(const float4*)&Qg[(size_t)(q0 + row) * DK + c4];
    }

    float m[4], l[4];
    float o[4][8];
#pragma unroll
    for (int r = 0; r < 4; ++r) {
        m[r] = -INFINITY; l[r] = 0.f;
#pragma unroll
        for (int c = 0; c < 8; ++c) o[r][c] = 0.f;
    }
    const float scale = 0.08838834764831845f;  // 1/sqrt(128)

    const int ntiles = blockIdx.x + 1;
    for (int kt = 0; kt < ntiles; ++kt) {
        const int k0 = kt * 64;
        __syncthreads();   // previous iteration's Ps/Vs reads done
#pragma unroll
        for (int t = 0; t < 8; ++t) {
            int e = t * 256 + tid;
            int row = e >> 5, c4 = (e & 31) << 2;
            *(float4*)&Ks[row * QS_LD + c4] = *(const float4*)&Kg[(size_t)(k0 + row) * DK + c4];
            *(float4*)&Vs[row * QS_LD + c4] = *(const float4*)&Vg[(size_t)(k0 + row) * DK + c4];
        }
        __syncthreads();

        // S = Q K^T
        float s[4][4];
#pragma unroll
        for (int r = 0; r < 4; ++r)
#pragma unroll
            for (int c = 0; c < 4; ++c) s[r][c] = 0.f;

#pragma unroll 4
        for (int d = 0; d < DK; d += 4) {
            float4 qa[4], kb[4];
#pragma unroll
            for (int r = 0; r < 4; ++r) qa[r] = *(float4*)&Qs[(ty * 4 + r) * QS_LD + d];
#pragma unroll
            for (int c = 0; c < 4; ++c) kb[c] = *(float4*)&Ks[(tx * 4 + c) * QS_LD + d];
#pragma unroll
            for (int r = 0; r < 4; ++r)
#pragma unroll
                for (int c = 0; c < 4; ++c) {
                    s[r][c] = fmaf(qa[r].x, kb[c].x, s[r][c]);
                    s[r][c] = fmaf(qa[r].y, kb[c].y, s[r][c]);
                    s[r][c] = fmaf(qa[r].z, kb[c].z, s[r][c]);
                    s[r][c] = fmaf(qa[r].w, kb[c].w, s[r][c]);
                }
        }

        // scale + causal mask + online softmax update
#pragma unroll
        for (int r = 0; r < 4; ++r) {
            const int qg = q0 + ty * 4 + r;
            float mx = -INFINITY;
#pragma unroll
            for (int c = 0; c < 4; ++c) {
                const int kg = k0 + tx * 4 + c;
                float v = s[r][c] * scale;
                if (kg > qg) v = -INFINITY;
                s[r][c] = v;
                mx = fmaxf(mx, v);
            }
            // reduce max over the 16 threads of this row group
#pragma unroll
            for (int w = 8; w >= 1; w >>= 1)
                mx = fmaxf(mx, __shfl_xor_sync(0xffffffffu, mx, w));
            const float mnew = fmaxf(m[r], mx);
            const float alpha = __expf(m[r] - mnew);   // m=-inf first iter -> 0
            float sum = 0.f;
#pragma unroll
            for (int c = 0; c < 4; ++c) {
                float p = __expf(s[r][c] - mnew);      // -inf -> 0
                sum += p;
                Ps[(ty * 4 + r) * PS_LD + tx * 4 + c] = p;
            }
#pragma unroll
            for (int w = 8; w >= 1; w >>= 1)
                sum += __shfl_xor_sync(0xffffffffu, sum, w);
            l[r] = l[r] * alpha + sum;
            m[r] = mnew;
#pragma unroll
            for (int c = 0; c < 8; ++c) o[r][c] *= alpha;
        }
        __syncthreads();   // Ps visible to all

        // O += P * V
#pragma unroll 4
        for (int j = 0; j < 64; ++j) {
            float pr[4];
#pragma unroll
            for (int r = 0; r < 4; ++r) pr[r] = Ps[(ty * 4 + r) * PS_LD + j];
            float4 v0 = *(float4*)&Vs[j * QS_LD + tx * 8];
            float4 v1 = *(float4*)&Vs[j * QS_LD + tx * 8 + 4];
#pragma unroll
            for (int r = 0; r < 4; ++r) {
                o[r][0] = fmaf(pr[r], v0.x, o[r][0]);
                o[r][1] = fmaf(pr[r], v0.y, o[r][1]);
                o[r][2] = fmaf(pr[r], v0.z, o[r][2]);
                o[r][3] = fmaf(pr[r], v0.w, o[r][3]);
                o[r][4] = fmaf(pr[r], v1.x, o[r][4]);
                o[r][5] = fmaf(pr[r], v1.y, o[r][5]);
                o[r][6] = fmaf(pr[r], v1.z, o[r][6]);
                o[r][7] = fmaf(pr[r], v1.w, o[r][7]);
            }
        }
    }

    // normalize + store
    float* Og = g_O + (size_t)b * SEQ * DK;
#pragma unroll
    for (int r = 0; r < 4; ++r) {
        const float inv = 1.f / l[r];
        const int row = q0 + ty * 4 + r;
        float4 w0 = make_float4(o[r][0]*inv, o[r][1]*inv, o[r][2]*inv, o[r][3]*inv);
        float4 w1 = make_float4(o[r][4]*inv, o[r][5]*inv, o[r][6]*inv, o[r][7]*inv);
        *(float4*)&Og[(size_t)row * DK + tx * 8]     = w0;
        *(float4*)&Og[(size_t)row * DK + tx * 8 + 4] = w1;
    }
}

// ---------------- launch ------------------------------------------------------
extern "C" void kernel_launch(void* const* d_in, const int* in_sizes, int n_in,
                              void* d_out, int out_size)
{
    const float* x  = (const float*)d_in[0];
    const float* Wq = (const float*)d_in[1];
    const float* Wk = (const float*)d_in[2];
    const float* Wv = (const float*)d_in[3];
    const float* Wo = (const float*)d_in[4];
    float* out = (float*)d_out;

    cudaFuncSetAttribute(flash_attn_kernel,
                         cudaFuncAttributeMaxDynamicSharedMemorySize, (int)ATT_SMEM);

    // 1) QKV projections: M=8192, N=128, K=1024; grid (n_tiles=1, m_tiles=128, 3)
    {
        dim3 grid(1, MTOT / BM, 3);
        qkv_gemm_kernel<<<grid, 256>>>(x, Wq, Wk, Wv);
    }
    // 2) causal flash attention
    {
        dim3 grid(SEQ / 64, BATCH);
        flash_attn_kernel<<<grid, 256, ATT_SMEM>>>();
    }
    // 3) output projection: M=8192, N=1024, K=128
    {
        dim3 grid(DMODEL / BN, MTOT / BM);
        out_gemm_kernel<<<grid, 256>>>(Wo, out);
    }
}

// round 8
// speedup vs baseline: 1.5677x; 1.5677x over previous
#include <cuda_runtime.h>
#include <cuda_bf16.h>
#include <math.h>

// Problem dims (fixed per reference)
#define BATCH 4
#define SEQ   2048
#define DMODEL 1024
#define DK    128
#define MTOT  (BATCH*SEQ)   // 8192

// ---------------- scratch (device globals; no allocation allowed) -----------
__device__ float g_Q[MTOT * DK];
__device__ float g_K[MTOT * DK];
__device__ float g_V[MTOT * DK];
__device__ float g_O[MTOT * DK];

// split-KV partials: [B][32 q-tiles][4 chunks][64 rows][128 cols]
__device__ float g_pO[BATCH * 32 * 4 * 64 * 128];
__device__ float g_pm[BATCH * 32 * 4 * 64];
__device__ float g_pl[BATCH * 32 * 4 * 64];

// ---------------- generic 64x128 SGEMM body (double buffered) ----------------
// C[M,N] = A[M,K] * B[K,N], row-major. BM=64, BN=128, BK=16, 256 threads.
#define BM 64
#define BN 128
#define BKG 16
#define AS_LD 68   // padded

__device__ __forceinline__ void sgemm_body(
    const float* __restrict__ A, const float* __restrict__ B, float* __restrict__ C,
    int N, int K, int m0, int n0,
    float (*As)[AS_LD], float (*Bs)[BN])   // As[2*BKG][AS_LD], Bs[2*BKG][BN]
{
    const int tid = threadIdx.x;
    const int tx = tid & 31;        // 0..31  (col groups of 4)
    const int ty = tid >> 5;        // 0..7   (row groups of 8)

    const int arow = tid >> 2;          // 0..63
    const int acol = (tid & 3) << 2;    // 0,4,8,12
    const int brow = tid >> 5;          // 0..7
    const int bcol = (tid & 31) << 2;   // 0..124

    const float* Ap = A + (size_t)(m0 + arow) * K + acol;

    float acc[8][4];
#pragma unroll
    for (int r = 0; r < 8; ++r)
#pragma unroll
        for (int c = 0; c < 4; ++c) acc[r][c] = 0.f;

    // preload tile 0 into buffer 0
    {
        float4 a  = *(const float4*)Ap;
        float4 b0 = *(const float4*)(B + (size_t)brow * N + n0 + bcol);
        float4 b1 = *(const float4*)(B + (size_t)(brow + 8) * N + n0 + bcol);
        As[acol + 0][arow] = a.x;
        As[acol + 1][arow] = a.y;
        As[acol + 2][arow] = a.z;
        As[acol + 3][arow] = a.w;
        *(float4*)&Bs[brow][bcol]     = b0;
        *(float4*)&Bs[brow + 8][bcol] = b1;
    }
    __syncthreads();

    const int nk = K / BKG;
    for (int it = 0; it < nk; ++it) {
        const int cur = (it & 1) * BKG;
        float4 an, bn0, bn1;
        const bool has_next = (it + 1 < nk);
        if (has_next) {
            const int koff = (it + 1) * BKG;
            an  = *(const float4*)(Ap + koff);
            bn0 = *(const float4*)(B + (size_t)(koff + brow) * N + n0 + bcol);
            bn1 = *(const float4*)(B + (size_t)(koff + brow + 8) * N + n0 + bcol);
        }
#pragma unroll
        for (int k = 0; k < BKG; ++k) {
            float4 a0 = *(float4*)&As[cur + k][ty * 8];
            float4 a1 = *(float4*)&As[cur + k][ty * 8 + 4];
            float4 bb = *(float4*)&Bs[cur + k][tx * 4];
            float ar[8] = {a0.x,a0.y,a0.z,a0.w,a1.x,a1.y,a1.z,a1.w};
            float br[4] = {bb.x,bb.y,bb.z,bb.w};
#pragma unroll
            for (int r = 0; r < 8; ++r)
#pragma unroll
                for (int c = 0; c < 4; ++c)
                    acc[r][c] = fmaf(ar[r], br[c], acc[r][c]);
        }
        if (has_next) {
            const int nxt = ((it + 1) & 1) * BKG;
            As[nxt + acol + 0][arow] = an.x;
            As[nxt + acol + 1][arow] = an.y;
            As[nxt + acol + 2][arow] = an.z;
            As[nxt + acol + 3][arow] = an.w;
            *(float4*)&Bs[nxt + brow][bcol]     = bn0;
            *(float4*)&Bs[nxt + brow + 8][bcol] = bn1;
            __syncthreads();
        }
    }
#pragma unroll
    for (int r = 0; r < 8; ++r) {
        float4 o = make_float4(acc[r][0], acc[r][1], acc[r][2], acc[r][3]);
        *(float4*)&C[(size_t)(m0 + ty * 8 + r) * N + n0 + tx * 4] = o;
    }
}

// QKV projection: grid (1, M/64, 3)
__global__ __launch_bounds__(256) void qkv_gemm_kernel(
    const float* __restrict__ x,
    const float* __restrict__ Wq,
    const float* __restrict__ Wk,
    const float* __restrict__ Wv)
{
    __shared__ float As[2 * BKG][AS_LD];
    __shared__ float Bs[2 * BKG][BN];
    const float* W;
    float* out;
    if (blockIdx.z == 0)      { W = Wq; out = g_Q; }
    else if (blockIdx.z == 1) { W = Wk; out = g_K; }
    else                      { W = Wv; out = g_V; }
    sgemm_body(x, W, out, DK, DMODEL, blockIdx.y * BM, blockIdx.x * BN, As, Bs);
}

// Output projection: grid (DMODEL/128, M/64)
__global__ __launch_bounds__(256) void out_gemm_kernel(
    const float* __restrict__ Wo, float* __restrict__ out)
{
    __shared__ float As[2 * BKG][AS_LD];
    __shared__ float Bs[2 * BKG][BN];
    sgemm_body(g_O, Wo, out, DMODEL, DK, blockIdx.y * BM, blockIdx.x * BN, As, Bs);
}

// ---------------- flash attention phase 1: split-KV partials -----------------
// BQ=64, BKV=64, DH=128. 256 threads = 16x16.
// KV chunks of 8 kv-tiles (512 rows). Block list per batch (80 blocks):
//   qi in [0,8):   1 chunk;  [8,16): 2;  [16,24): 3;  [24,32): 4.
#define QS_LD 132
#define PS_LD 65
#define ATT_SMEM ((3 * 64 * QS_LD + 64 * PS_LD) * sizeof(float))
#define NEG_BIG (-1e30f)

__global__ __launch_bounds__(256) void attn_partial_kernel()
{
    extern __shared__ float sm[];
    float* Qs = sm;                     // 64 x 132
    float* Ks = Qs + 64 * QS_LD;        // 64 x 132
    float* Vs = Ks + 64 * QS_LD;        // 64 x 132
    float* Ps = Vs + 64 * QS_LD;        // 64 x 65

    const int tid = threadIdx.x;
    const int tx = tid & 15;
    const int ty = tid >> 4;
    const int b  = blockIdx.y;

    // decode (q-tile, chunk) from flattened block index
    int qi, ch;
    {
        const int i = blockIdx.x;
        if (i < 8)       { qi = i;               ch = 0; }
        else if (i < 24) { int j = i - 8;  qi = 8  + (j >> 1); ch = j & 1; }
        else if (i < 48) { int j = i - 24; qi = 16 + j / 3;    ch = j - (j / 3) * 3; }
        else             { int j = i - 48; qi = 24 + (j >> 2); ch = j & 3; }
    }
    const int q0 = qi * 64;
    const int kt_begin = ch * 8;
    const int kt_end   = min(kt_begin + 8, qi + 1);

    const float* Qg = g_Q + (size_t)b * SEQ * DK;
    const float* Kg = g_K + (size_t)b * SEQ * DK;
    const float* Vg = g_V + (size_t)b * SEQ * DK;

    // load Q tile
#pragma unroll
    for (int t = 0; t < 8; ++t) {
        int e = t * 256 + tid;               // float4 index, 0..2047
        int row = e >> 5, c4 = (e & 31) << 2;
        *(float4*)&Qs[row * QS_LD + c4] = *(const float4*)&Qg[(size_t)(q0 + row) * DK + c4];
    }

    float m[4], l[4];
    float o[4][8];
#pragma unroll
    for (int r = 0; r < 4; ++r) {
        m[r] = NEG_BIG; l[r] = 0.f;
#pragma unroll
        for (int c = 0; c < 8; ++c) o[r][c] = 0.f;
    }
    const float scale = 0.08838834764831845f;  // 1/sqrt(128)

    for (int kt = kt_begin; kt < kt_end; ++kt) {
        const int k0 = kt * 64;
        const bool diag = (kt == qi);
        __syncthreads();   // previous iteration's Ps/Vs reads done
#pragma unroll
        for (int t = 0; t < 8; ++t) {
            int e = t * 256 + tid;
            int row = e >> 5, c4 = (e & 31) << 2;
            *(float4*)&Ks[row * QS_LD + c4] = *(const float4*)&Kg[(size_t)(k0 + row) * DK + c4];
            *(float4*)&Vs[row * QS_LD + c4] = *(const float4*)&Vg[(size_t)(k0 + row) * DK + c4];
        }
        __syncthreads();

        // S = Q K^T
        float s[4][4];
#pragma unroll
        for (int r = 0; r < 4; ++r)
#pragma unroll
            for (int c = 0; c < 4; ++c) s[r][c] = 0.f;

#pragma unroll 4
        for (int d = 0; d < DK; d += 4) {
            float4 qa[4], kb[4];
#pragma unroll
            for (int r = 0; r < 4; ++r) qa[r] = *(float4*)&Qs[(ty * 4 + r) * QS_LD + d];
#pragma unroll
            for (int c = 0; c < 4; ++c) kb[c] = *(float4*)&Ks[(tx * 4 + c) * QS_LD + d];
#pragma unroll
            for (int r = 0; r < 4; ++r)
#pragma unroll
                for (int c = 0; c < 4; ++c) {
                    s[r][c] = fmaf(qa[r].x, kb[c].x, s[r][c]);
                    s[r][c] = fmaf(qa[r].y, kb[c].y, s[r][c]);
                    s[r][c] = fmaf(qa[r].z, kb[c].z, s[r][c]);
                    s[r][c] = fmaf(qa[r].w, kb[c].w, s[r][c]);
                }
        }

        // scale + (diagonal) causal mask + online softmax update
#pragma unroll
        for (int r = 0; r < 4; ++r) {
            const int qg = q0 + ty * 4 + r;
            float mx = NEG_BIG;
#pragma unroll
            for (int c = 0; c < 4; ++c) {
                float v = s[r][c] * scale;
                if (diag) {
                    const int kg = k0 + tx * 4 + c;
                    if (kg > qg) v = NEG_BIG;
                }
                s[r][c] = v;
                mx = fmaxf(mx, v);
            }
            // reduce max over the 16 threads of this row group
#pragma unroll
            for (int w = 8; w >= 1; w >>= 1)
                mx = fmaxf(mx, __shfl_xor_sync(0xffffffffu, mx, w));
            const float mnew = fmaxf(m[r], mx);
            const float alpha = __expf(m[r] - mnew);   // underflows to 0 on first tile
            float sum = 0.f;
#pragma unroll
            for (int c = 0; c < 4; ++c) {
                float p = __expf(s[r][c] - mnew);      // masked -> exp(-huge) -> 0
                sum += p;
                Ps[(ty * 4 + r) * PS_LD + tx * 4 + c] = p;
            }
#pragma unroll
            for (int w = 8; w >= 1; w >>= 1)
                sum += __shfl_xor_sync(0xffffffffu, sum, w);
            l[r] = l[r] * alpha + sum;
            m[r] = mnew;
#pragma unroll
            for (int c = 0; c < 8; ++c) o[r][c] *= alpha;
        }
        __syncthreads();   // Ps visible to all

        // O += P * V
#pragma unroll 4
        for (int j = 0; j < 64; ++j) {
            float pr[4];
#pragma unroll
            for (int r = 0; r < 4; ++r) pr[r] = Ps[(ty * 4 + r) * PS_LD + j];
            float4 v0 = *(float4*)&Vs[j * QS_LD + tx * 8];
            float4 v1 = *(float4*)&Vs[j * QS_LD + tx * 8 + 4];
#pragma unroll
            for (int r = 0; r < 4; ++r) {
                o[r][0] = fmaf(pr[r], v0.x, o[r][0]);
                o[r][1] = fmaf(pr[r], v0.y, o[r][1]);
                o[r][2] = fmaf(pr[r], v0.z, o[r][2]);
                o[r][3] = fmaf(pr[r], v0.w, o[r][3]);
                o[r][4] = fmaf(pr[r], v1.x, o[r][4]);
                o[r][5] = fmaf(pr[r], v1.y, o[r][5]);
                o[r][6] = fmaf(pr[r], v1.z, o[r][6]);
                o[r][7] = fmaf(pr[r], v1.w, o[r][7]);
            }
        }
    }

    // store UNNORMALIZED partial O + per-row (m, l)
    const int slot = (b * 32 + qi) * 4 + ch;
    float* pO = g_pO + (size_t)slot * (64 * 128);
#pragma unroll
    for (int r = 0; r < 4; ++r) {
        const int row = ty * 4 + r;
        float4 w0 = make_float4(o[r][0], o[r][1], o[r][2], o[r][3]);
        float4 w1 = make_float4(o[r][4], o[r][5], o[r][6], o[r][7]);
        *(float4*)&pO[(size_t)row * 128 + tx * 8]     = w0;
        *(float4*)&pO[(size_t)row * 128 + tx * 8 + 4] = w1;
        if (tx == 0) {
            g_pm[slot * 64 + row] = m[r];
            g_pl[slot * 64 + row] = l[r];
        }
    }
}

// ---------------- flash attention phase 2: merge partials ---------------------
// grid (32, 4), 256 threads. Thread: row = tid>>2 (0..63), 32-col group = (tid&3)*32.
__global__ __launch_bounds__(256) void attn_merge_kernel()
{
    const int qi = blockIdx.x;
    const int b  = blockIdx.y;
    const int nc = (qi >> 3) + 1;
    const int tid = threadIdx.x;
    const int r  = tid >> 2;
    const int cg = (tid & 3) << 5;
    const int base = (b * 32 + qi) * 4;

    float mc[4], wc[4];
    float mstar = NEG_BIG;
    for (int c = 0; c < nc; ++c) {
        mc[c] = g_pm[(base + c) * 64 + r];
        mstar = fmaxf(mstar, mc[c]);
    }
    float L = 0.f;
    for (int c = 0; c < nc; ++c) {
        wc[c] = __expf(mc[c] - mstar);
        L += wc[c] * g_pl[(base + c) * 64 + r];
    }
    const float inv = 1.f / L;

    float acc[32];
#pragma unroll
    for (int j = 0; j < 32; ++j) acc[j] = 0.f;

    for (int c = 0; c < nc; ++c) {
        const float w = wc[c];
        const float* src = g_pO + (size_t)(base + c) * (64 * 128) + (size_t)r * 128 + cg;
#pragma unroll
        for (int v = 0; v < 8; ++v) {
            float4 t = *(const float4*)&src[v * 4];
            acc[v*4+0] = fmaf(w, t.x, acc[v*4+0]);
            acc[v*4+1] = fmaf(w, t.y, acc[v*4+1]);
            acc[v*4+2] = fmaf(w, t.z, acc[v*4+2]);
            acc[v*4+3] = fmaf(w, t.w, acc[v*4+3]);
        }
    }

    float* dst = g_O + (size_t)b * SEQ * DK + (size_t)(qi * 64 + r) * 128 + cg;
#pragma unroll
    for (int v = 0; v < 8; ++v) {
        float4 t = make_float4(acc[v*4+0]*inv, acc[v*4+1]*inv, acc[v*4+2]*inv, acc[v*4+3]*inv);
        *(float4*)&dst[v * 4] = t;
    }
}

// ---------------- launch ------------------------------------------------------
extern "C" void kernel_launch(void* const* d_in, const int* in_sizes, int n_in,
                              void* d_out, int out_size)
{
    const float* x  = (const float*)d_in[0];
    const float* Wq = (const float*)d_in[1];
    const float* Wk = (const float*)d_in[2];
    const float* Wv = (const float*)d_in[3];
    const float* Wo = (const float*)d_in[4];
    float* out = (float*)d_out;

    cudaFuncSetAttribute(attn_partial_kernel,
                         cudaFuncAttributeMaxDynamicSharedMemorySize, (int)ATT_SMEM);

    // 1) QKV projections: M=8192, N=128, K=1024
    {
        dim3 grid(1, MTOT / BM, 3);
        qkv_gemm_kernel<<<grid, 256>>>(x, Wq, Wk, Wv);
    }
    // 2a) causal flash attention, split-KV partials (80 blocks/batch)
    {
        dim3 grid(80, BATCH);
        attn_partial_kernel<<<grid, 256, ATT_SMEM>>>();
    }
    // 2b) merge partials
    {
        dim3 grid(32, BATCH);
        attn_merge_kernel<<<grid, 256>>>();
    }
    // 3) output projection: M=8192, N=1024, K=128
    {
        dim3 grid(DMODEL / BN, MTOT / BM);
        out_gemm_kernel<<<grid, 256>>>(Wo, out);
    }
}

// round 9
// speedup vs baseline: 4.5634x; 2.9109x over previous
#include <cuda_runtime.h>
#include <cuda_bf16.h>
#include <math.h>

// Problem dims (fixed per reference)
#define BATCH 4
#define SEQ   2048
#define DMODEL 1024
#define DK    128
#define MTOT  (BATCH*SEQ)   // 8192
#define NEG_BIG (-1e30f)

// ---------------- scratch (device globals; no allocation allowed) -----------
__device__ float g_Q[MTOT * DK];
__device__ float g_K[MTOT * DK];
__device__ float g_V[MTOT * DK];
__device__ float g_O[MTOT * DK];

// split-KV partials: [B][32 q-tiles][4 chunks][64 rows][128 cols]
__device__ float g_pO[BATCH * 32 * 4 * 64 * 128];
__device__ float g_pm[BATCH * 32 * 4 * 64];
__device__ float g_pl[BATCH * 32 * 4 * 64];

// ---------------- tf32 helpers ------------------------------------------------
__device__ __forceinline__ unsigned f2tf(float x) {
    unsigned r;
    asm("cvt.rna.tf32.f32 %0, %1;" : "=r"(r) : "f"(x));
    return r;
}
__device__ __forceinline__ float f2tf_f(float x) { return __uint_as_float(f2tf(x)); }

// D = A(16x8, row) * B(8x8, col) + D, tf32 inputs, fp32 accum.
__device__ __forceinline__ void mma8(float* c, const unsigned* a, unsigned b0, unsigned b1) {
    asm volatile(
        "mma.sync.aligned.m16n8k8.row.col.f32.tf32.tf32.f32 "
        "{%0,%1,%2,%3},{%4,%5,%6,%7},{%8,%9},{%0,%1,%2,%3};"
        : "+f"(c[0]), "+f"(c[1]), "+f"(c[2]), "+f"(c[3])
        : "r"(a[0]), "r"(a[1]), "r"(a[2]), "r"(a[3]), "r"(b0), "r"(b1));
}

// ---------------- tf32 MMA GEMM body ------------------------------------------
// C[M,N] = A[M,K]*B[K,N] row-major. BM=64, BN=128, BK=16, 256 threads (8 warps).
// Warp grid 4(m) x 2(n); warp tile m16 x n64. Inputs rounded to tf32 at smem store.
#define G_BM 64
#define G_BN 128
#define G_BK 16
#define A_LD 20     // conflict-free A-fragment gathers
#define B_LD 136    // conflict-free B-fragment gathers, 16B-aligned rows

template<bool ROUND_OUT>
__device__ __forceinline__ void mma_gemm(
    const float* __restrict__ A, const float* __restrict__ B, float* __restrict__ C,
    int N, int K, int m0, int n0,
    float (*As)[G_BM][A_LD], float (*Bs)[G_BK][B_LD])
{
    const int tid  = threadIdx.x;
    const int lane = tid & 31, wid = tid >> 5;
    const int gid  = lane >> 2, tg = lane & 3;
    const int wm   = (wid & 3) * 16;
    const int wn   = (wid >> 2) * 64;

    const int ar = tid >> 2, ac = (tid & 3) << 2;        // A tile: 64x16
    const int br = tid >> 5, bc = (tid & 31) << 2;       // B tile: 16x128

    const float* Ap  = A + (size_t)(m0 + ar) * K + ac;
    const float* Bp0 = B + (size_t)br * N + n0 + bc;
    const float* Bp1 = B + (size_t)(br + 8) * N + n0 + bc;

    float acc[8][4];
#pragma unroll
    for (int nb = 0; nb < 8; ++nb)
#pragma unroll
        for (int j = 0; j < 4; ++j) acc[nb][j] = 0.f;

    // preload tile 0 (rounded to tf32)
    {
        float4 a  = *(const float4*)Ap;
        float4 b0 = *(const float4*)Bp0;
        float4 b1 = *(const float4*)Bp1;
        As[0][ar][ac+0] = f2tf_f(a.x);  As[0][ar][ac+1] = f2tf_f(a.y);
        As[0][ar][ac+2] = f2tf_f(a.z);  As[0][ar][ac+3] = f2tf_f(a.w);
        Bs[0][br][bc+0]   = f2tf_f(b0.x); Bs[0][br][bc+1]   = f2tf_f(b0.y);
        Bs[0][br][bc+2]   = f2tf_f(b0.z); Bs[0][br][bc+3]   = f2tf_f(b0.w);
        Bs[0][br+8][bc+0] = f2tf_f(b1.x); Bs[0][br+8][bc+1] = f2tf_f(b1.y);
        Bs[0][br+8][bc+2] = f2tf_f(b1.z); Bs[0][br+8][bc+3] = f2tf_f(b1.w);
    }
    __syncthreads();

    const int nk = K / G_BK;
    for (int it = 0; it < nk; ++it) {
        const int buf = it & 1;
        const bool hn = (it + 1 < nk);
        float4 an, bn0, bn1;
        if (hn) {
            an  = *(const float4*)(Ap + (it + 1) * G_BK);
            bn0 = *(const float4*)(Bp0 + (size_t)(it + 1) * G_BK * N);
            bn1 = *(const float4*)(Bp1 + (size_t)(it + 1) * G_BK * N);
        }
#pragma unroll
        for (int kc = 0; kc < 2; ++kc) {
            unsigned a[4];
            a[0] = __float_as_uint(As[buf][wm + gid    ][kc*8 + tg    ]);
            a[1] = __float_as_uint(As[buf][wm + gid + 8][kc*8 + tg    ]);
            a[2] = __float_as_uint(As[buf][wm + gid    ][kc*8 + tg + 4]);
            a[3] = __float_as_uint(As[buf][wm + gid + 8][kc*8 + tg + 4]);
#pragma unroll
            for (int nb = 0; nb < 8; ++nb) {
                unsigned b0 = __float_as_uint(Bs[buf][kc*8 + tg    ][wn + nb*8 + gid]);
                unsigned b1 = __float_as_uint(Bs[buf][kc*8 + tg + 4][wn + nb*8 + gid]);
                mma8(acc[nb], a, b0, b1);
            }
        }
        if (hn) {
            const int nxt = buf ^ 1;
            As[nxt][ar][ac+0] = f2tf_f(an.x);  As[nxt][ar][ac+1] = f2tf_f(an.y);
            As[nxt][ar][ac+2] = f2tf_f(an.z);  As[nxt][ar][ac+3] = f2tf_f(an.w);
            Bs[nxt][br][bc+0]   = f2tf_f(bn0.x); Bs[nxt][br][bc+1]   = f2tf_f(bn0.y);
            Bs[nxt][br][bc+2]   = f2tf_f(bn0.z); Bs[nxt][br][bc+3]   = f2tf_f(bn0.w);
            Bs[nxt][br+8][bc+0] = f2tf_f(bn1.x); Bs[nxt][br+8][bc+1] = f2tf_f(bn1.y);
            Bs[nxt][br+8][bc+2] = f2tf_f(bn1.z); Bs[nxt][br+8][bc+3] = f2tf_f(bn1.w);
            __syncthreads();
        }
    }

    // epilogue: C frag rows {wm+gid, wm+gid+8}, cols {wn+nb*8+2tg, +1}
#pragma unroll
    for (int nb = 0; nb < 8; ++nb) {
        const int row = m0 + wm + gid;
        const int col = n0 + wn + nb*8 + 2*tg;
        float2 v0, v1;
        if (ROUND_OUT) {
            v0 = make_float2(f2tf_f(acc[nb][0]), f2tf_f(acc[nb][1]));
            v1 = make_float2(f2tf_f(acc[nb][2]), f2tf_f(acc[nb][3]));
        } else {
            v0 = make_float2(acc[nb][0], acc[nb][1]);
            v1 = make_float2(acc[nb][2], acc[nb][3]);
        }
        *(float2*)&C[(size_t)row * N + col]       = v0;
        *(float2*)&C[(size_t)(row + 8) * N + col] = v1;
    }
}

// QKV projection: grid (1, M/64, 3). Outputs rounded to tf32 for attention.
__global__ __launch_bounds__(256) void qkv_gemm_kernel(
    const float* __restrict__ x,
    const float* __restrict__ Wq,
    const float* __restrict__ Wk,
    const float* __restrict__ Wv)
{
    __shared__ float As[2][G_BM][A_LD];
    __shared__ float Bs[2][G_BK][B_LD];
    const float* W; float* out;
    if (blockIdx.z == 0)      { W = Wq; out = g_Q; }
    else if (blockIdx.z == 1) { W = Wk; out = g_K; }
    else                      { W = Wv; out = g_V; }
    mma_gemm<true>(x, W, out, DK, DMODEL, blockIdx.y * G_BM, 0, As, Bs);
}

// Output projection: grid (DMODEL/128, M/64)
__global__ __launch_bounds__(256) void out_gemm_kernel(
    const float* __restrict__ Wo, float* __restrict__ out)
{
    __shared__ float As[2][G_BM][A_LD];
    __shared__ float Bs[2][G_BK][B_LD];
    mma_gemm<false>(g_O, Wo, out, DMODEL, DK, blockIdx.y * G_BM, blockIdx.x * G_BN, As, Bs);
}

// ---------------- flash attention phase 1: split-KV, tf32 mma -----------------
// BQ=64, BKV=64, DH=128. 128 threads = 4 warps; warp w owns q-rows [16w,16w+16).
// Q fragments register-resident; softmax fragment-resident; P through smem.
#define K_LD 136
#define PS_LD 72
#define ATT_SMEM ((2 * 64 * K_LD + 64 * PS_LD) * sizeof(float))

__global__ __launch_bounds__(128) void attn_partial_kernel()
{
    extern __shared__ float sm[];
    float* Ks = sm;                   // 64 x 136
    float* Vs = Ks + 64 * K_LD;       // 64 x 136
    float* Ps = Vs + 64 * K_LD;       // 64 x 72

    const int tid  = threadIdx.x;
    const int lane = tid & 31, wid = tid >> 5;
    const int gid  = lane >> 2, tg = lane & 3;
    const int b    = blockIdx.y;

    // decode (q-tile, chunk) from flattened block index
    int qi, ch;
    {
        const int i = blockIdx.x;
        if (i < 8)       { qi = i;               ch = 0; }
        else if (i < 24) { int j = i - 8;  qi = 8  + (j >> 1); ch = j & 1; }
        else if (i < 48) { int j = i - 24; qi = 16 + j / 3;    ch = j - (j / 3) * 3; }
        else             { int j = i - 48; qi = 24 + (j >> 2); ch = j & 3; }
    }
    const int q0 = qi * 64;
    const int kt_begin = ch * 8;
    const int kt_end   = min(kt_begin + 8, qi + 1);

    const float* Qg = g_Q + (size_t)b * SEQ * DK;
    const float* Kg = g_K + (size_t)b * SEQ * DK;
    const float* Vg = g_V + (size_t)b * SEQ * DK;

    const int r0 = wid * 16 + gid;   // warp-local A-fragment base row

    // stage Q tile through Ks, extract register fragments (already tf32-rounded)
#pragma unroll
    for (int t = 0; t < 16; ++t) {
        int e = t * 128 + tid;                 // float4 index, 0..2047
        int row = e >> 5, c4 = (e & 31) << 2;
        *(float4*)&Ks[row * K_LD + c4] = *(const float4*)&Qg[(size_t)(q0 + row) * DK + c4];
    }
    __syncthreads();
    unsigned qa[16][4];
#pragma unroll
    for (int kc = 0; kc < 16; ++kc) {
        qa[kc][0] = __float_as_uint(Ks[(r0    ) * K_LD + kc*8 + tg    ]);
        qa[kc][1] = __float_as_uint(Ks[(r0 + 8) * K_LD + kc*8 + tg    ]);
        qa[kc][2] = __float_as_uint(Ks[(r0    ) * K_LD + kc*8 + tg + 4]);
        qa[kc][3] = __float_as_uint(Ks[(r0 + 8) * K_LD + kc*8 + tg + 4]);
    }
    __syncthreads();

    float ob[16][4];
#pragma unroll
    for (int nb = 0; nb < 16; ++nb)
#pragma unroll
        for (int j = 0; j < 4; ++j) ob[nb][j] = 0.f;
    float m[2] = {NEG_BIG, NEG_BIG}, l[2] = {0.f, 0.f};
    const float scale = 0.08838834764831845f;  // 1/sqrt(128)

    for (int kt = kt_begin; kt < kt_end; ++kt) {
        const int k0 = kt * 64;
        const bool diag = (kt == qi);

        // load K, V tiles
#pragma unroll
        for (int t = 0; t < 16; ++t) {
            int e = t * 128 + tid;
            int row = e >> 5, c4 = (e & 31) << 2;
            *(float4*)&Ks[row * K_LD + c4] = *(const float4*)&Kg[(size_t)(k0 + row) * DK + c4];
            *(float4*)&Vs[row * K_LD + c4] = *(const float4*)&Vg[(size_t)(k0 + row) * DK + c4];
        }
        __syncthreads();

        // S = Q K^T  (warp: m16 x n64, k=128)
        float sc[8][4];
#pragma unroll
        for (int nb = 0; nb < 8; ++nb)
#pragma unroll
            for (int j = 0; j < 4; ++j) sc[nb][j] = 0.f;

#pragma unroll
        for (int kc = 0; kc < 16; ++kc) {
#pragma unroll
            for (int nb = 0; nb < 8; ++nb) {
                unsigned b0 = __float_as_uint(Ks[(nb*8 + gid) * K_LD + kc*8 + tg    ]);
                unsigned b1 = __float_as_uint(Ks[(nb*8 + gid) * K_LD + kc*8 + tg + 4]);
                mma8(sc[nb], qa[kc], b0, b1);
            }
        }

        // fragment-resident softmax (rows: r0 for c{0,1}, r0+8 for c{2,3})
#pragma unroll
        for (int r = 0; r < 2; ++r) {
            const int qg = q0 + r0 + r*8;
            float mx = NEG_BIG;
#pragma unroll
            for (int nb = 0; nb < 8; ++nb) {
#pragma unroll
                for (int j = 0; j < 2; ++j) {
                    float v = sc[nb][2*r + j] * scale;
                    if (diag) {
                        const int kg = k0 + nb*8 + 2*tg + j;
                        if (kg > qg) v = NEG_BIG;
                    }
                    sc[nb][2*r + j] = v;
                    mx = fmaxf(mx, v);
                }
            }
            mx = fmaxf(mx, __shfl_xor_sync(0xffffffffu, mx, 1));
            mx = fmaxf(mx, __shfl_xor_sync(0xffffffffu, mx, 2));
            const float mnew  = fmaxf(m[r], mx);
            const float alpha = __expf(m[r] - mnew);
            float sum = 0.f;
#pragma unroll
            for (int nb = 0; nb < 8; ++nb) {
                float p0 = __expf(sc[nb][2*r    ] - mnew);
                float p1 = __expf(sc[nb][2*r + 1] - mnew);
                sum += p0 + p1;
                float2 pv = make_float2(f2tf_f(p0), f2tf_f(p1));
                *(float2*)&Ps[(r0 + r*8) * PS_LD + nb*8 + 2*tg] = pv;
            }
            sum += __shfl_xor_sync(0xffffffffu, sum, 1);
            sum += __shfl_xor_sync(0xffffffffu, sum, 2);
            l[r] = l[r] * alpha + sum;
            m[r] = mnew;
#pragma unroll
            for (int nb = 0; nb < 16; ++nb) {
                ob[nb][2*r    ] *= alpha;
                ob[nb][2*r + 1] *= alpha;
            }
        }
        __syncthreads();   // Ps complete (warp-local, but keep warps in lockstep w/ tile loads)

        // O += P * V  (warp: m16 x n128, k=64)
#pragma unroll
        for (int kc = 0; kc < 8; ++kc) {
            unsigned pa[4];
            pa[0] = __float_as_uint(Ps[(r0    ) * PS_LD + kc*8 + tg    ]);
            pa[1] = __float_as_uint(Ps[(r0 + 8) * PS_LD + kc*8 + tg    ]);
            pa[2] = __float_as_uint(Ps[(r0    ) * PS_LD + kc*8 + tg + 4]);
            pa[3] = __float_as_uint(Ps[(r0 + 8) * PS_LD + kc*8 + tg + 4]);
#pragma unroll
            for (int nb = 0; nb < 16; ++nb) {
                unsigned b0 = __float_as_uint(Vs[(kc*8 + tg    ) * K_LD + nb*8 + gid]);
                unsigned b1 = __float_as_uint(Vs[(kc*8 + tg + 4) * K_LD + nb*8 + gid]);
                mma8(ob[nb], pa, b0, b1);
            }
        }
        __syncthreads();   // done reading Ks/Vs/Ps before next tile load
    }

    // store UNNORMALIZED partial O + per-row (m, l)
    const int slot = (b * 32 + qi) * 4 + ch;
    float* pO = g_pO + (size_t)slot * (64 * 128);
#pragma unroll
    for (int nb = 0; nb < 16; ++nb) {
        const int col = nb*8 + 2*tg;
        *(float2*)&pO[(size_t)(r0    ) * 128 + col] = make_float2(ob[nb][0], ob[nb][1]);
        *(float2*)&pO[(size_t)(r0 + 8) * 128 + col] = make_float2(ob[nb][2], ob[nb][3]);
    }
    if (tg == 0) {
        g_pm[slot * 64 + r0]     = m[0];
        g_pl[slot * 64 + r0]     = l[0];
        g_pm[slot * 64 + r0 + 8] = m[1];
        g_pl[slot * 64 + r0 + 8] = l[1];
    }
}

// ---------------- flash attention phase 2: merge partials ---------------------
__global__ __launch_bounds__(256) void attn_merge_kernel()
{
    const int qi = blockIdx.x;
    const int b  = blockIdx.y;
    const int nc = (qi >> 3) + 1;
    const int tid = threadIdx.x;
    const int r  = tid >> 2;
    const int cg = (tid & 3) << 5;
    const int base = (b * 32 + qi) * 4;

    float mc[4], wc[4];
    float mstar = NEG_BIG;
    for (int c = 0; c < nc; ++c) {
        mc[c] = g_pm[(base + c) * 64 + r];
        mstar = fmaxf(mstar, mc[c]);
    }
    float L = 0.f;
    for (int c = 0; c < nc; ++c) {
        wc[c] = __expf(mc[c] - mstar);
        L += wc[c] * g_pl[(base + c) * 64 + r];
    }
    const float inv = 1.f / L;

    float acc[32];
#pragma unroll
    for (int j = 0; j < 32; ++j) acc[j] = 0.f;

    for (int c = 0; c < nc; ++c) {
        const float w = wc[c];
        const float* src = g_pO + (size_t)(base + c) * (64 * 128) + (size_t)r * 128 + cg;
#pragma unroll
        for (int v = 0; v < 8; ++v) {
            float4 t = *(const float4*)&src[v * 4];
            acc[v*4+0] = fmaf(w, t.x, acc[v*4+0]);
            acc[v*4+1] = fmaf(w, t.y, acc[v*4+1]);
            acc[v*4+2] = fmaf(w, t.z, acc[v*4+2]);
            acc[v*4+3] = fmaf(w, t.w, acc[v*4+3]);
        }
    }

    float* dst = g_O + (size_t)b * SEQ * DK + (size_t)(qi * 64 + r) * 128 + cg;
#pragma unroll
    for (int v = 0; v < 8; ++v) {
        float4 t = make_float4(acc[v*4+0]*inv, acc[v*4+1]*inv, acc[v*4+2]*inv, acc[v*4+3]*inv);
        *(float4*)&dst[v * 4] = t;
    }
}

// ---------------- launch ------------------------------------------------------
extern "C" void kernel_launch(void* const* d_in, const int* in_sizes, int n_in,
                              void* d_out, int out_size)
{
    const float* x  = (const float*)d_in[0];
    const float* Wq = (const float*)d_in[1];
    const float* Wk = (const float*)d_in[2];
    const float* Wv = (const float*)d_in[3];
    const float* Wo = (const float*)d_in[4];
    float* out = (float*)d_out;

    cudaFuncSetAttribute(attn_partial_kernel,
                         cudaFuncAttributeMaxDynamicSharedMemorySize, (int)ATT_SMEM);

    // 1) QKV projections (tf32 mma): M=8192, N=128, K=1024
    {
        dim3 grid(1, MTOT / G_BM, 3);
        qkv_gemm_kernel<<<grid, 256>>>(x, Wq, Wk, Wv);
    }
    // 2a) causal flash attention, split-KV partials (80 blocks/batch, tf32 mma)
    {
        dim3 grid(80, BATCH);
        attn_partial_kernel<<<grid, 128, ATT_SMEM>>>();
    }
    // 2b) merge partials
    {
        dim3 grid(32, BATCH);
        attn_merge_kernel<<<grid, 256>>>();
    }
    // 3) output projection (tf32 mma): M=8192, N=1024, K=128
    {
        dim3 grid(DMODEL / G_BN, MTOT / G_BM);
        out_gemm_kernel<<<grid, 256>>>(Wo, out);
    }
}